// round 10
// baseline (speedup 1.0000x reference)
#include <cuda_runtime.h>
#include <math_constants.h>

#define N_ROWS 131072
#define FEAT   256
#define N_ANC  64
#define ANC    128
#define EPS    1e-5f

#define GRID1  296              // 2 blocks/SM -> whole grid co-resident (spin-safe)
#define BLOCK1 512
#define WARPS1 (BLOCK1/32)
#define STEP   (GRID1*WARPS1)   // 4736 warps

// scratch (no allocs allowed)
__device__ float d_partials[GRID1 * 260];    // per-block: A[256], m, Z, Q
__device__ float d_sr[FEAT];                 // sin(recv)
__device__ int   d_counter = 0;
__device__ int   d_flag    = 0;
__device__ int   d_done    = 0;

// ---------------- single fused kernel: prelude + phase1 (single-row) + merge + phase3 ----------------
__global__ void __launch_bounds__(BLOCK1, 2)
k_main(const float* __restrict__ feat,
       const float* __restrict__ W_send,
       const float* __restrict__ a_send,
       const float* __restrict__ anchors,
       const float* __restrict__ g_feat,
       const float* __restrict__ b_feat,
       const float* __restrict__ g_anc,
       const float* __restrict__ b_anc,
       const float* __restrict__ W_recv,
       float* __restrict__ out) {
    const int tid  = threadIdx.x;
    const int warp = tid >> 5;
    const int lane = tid & 31;
    const int gwarp = blockIdx.x * WARPS1 + warp;

    // ======== prelude: v = W_send @ a2 (SMEM), Sgv, Sbv ========
    __shared__ float sa2[ANC];
    __shared__ float sv[FEAT];
    __shared__ float prered[2 * WARPS1];
    __shared__ float sSgv, sSbv;

    if (tid < ANC) sa2[tid] = a_send[ANC + tid];
    __syncthreads();
    if (tid < FEAT) {
        const float* wr = W_send + tid * ANC;
        float s = 0.f;
        #pragma unroll 8
        for (int j = 0; j < ANC; j++) s += wr[j] * sa2[j];
        sv[tid] = s;
    }
    __syncthreads();
    {
        float p1 = 0.f, p2 = 0.f;
        if (tid < FEAT) {
            const float vv = sv[tid];
            p1 = g_feat[tid] * vv;
            p2 = b_feat[tid] * vv;
        }
        #pragma unroll
        for (int off = 16; off; off >>= 1) {
            p1 += __shfl_xor_sync(0xffffffffu, p1, off);
            p2 += __shfl_xor_sync(0xffffffffu, p2, off);
        }
        if (lane == 0) { prered[warp] = p1; prered[WARPS1 + warp] = p2; }
        __syncthreads();
        if (tid == 0) {
            float a = 0.f, b = 0.f;
            #pragma unroll
            for (int w = 0; w < WARPS1; w++) { a += prered[w]; b += prered[WARPS1 + w]; }
            sSgv = a; sSbv = b;
        }
        __syncthreads();
    }

    // per-lane gv constants (8 regs)
    float4 gv0, gv1;
    {
        const float4 g0 = *(const float4*)&g_feat[lane * 8];
        const float4 g1 = *(const float4*)&g_feat[lane * 8 + 4];
        gv0.x = sv[lane*8+0]*g0.x; gv0.y = sv[lane*8+1]*g0.y;
        gv0.z = sv[lane*8+2]*g0.z; gv0.w = sv[lane*8+3]*g0.w;
        gv1.x = sv[lane*8+4]*g1.x; gv1.y = sv[lane*8+5]*g1.y;
        gv1.z = sv[lane*8+6]*g1.z; gv1.w = sv[lane*8+7]*g1.w;
    }
    const float Sgv = sSgv, Sbv = sSbv;

    // ======== phase 1: single-row streaming loop (lean registers, no spills) ========
    float m = -CUDART_INF_F, Z = 0.f, Q = 0.f;
    float acc[8];
    #pragma unroll
    for (int j = 0; j < 8; j++) acc[j] = 0.f;

    for (int row = gwarp; row < N_ROWS; row += STEP) {
        const float4* rp = (const float4*)(feat + (size_t)row * FEAT);
        const float4 a0 = rp[lane * 2];
        const float4 a1 = rp[lane * 2 + 1];

        float s  = a0.x + a0.y + a0.z + a0.w + a1.x + a1.y + a1.z + a1.w;
        float sq = a0.x*a0.x + a0.y*a0.y + a0.z*a0.z + a0.w*a0.w
                 + a1.x*a1.x + a1.y*a1.y + a1.z*a1.z + a1.w*a1.w;
        float sx = a0.x*gv0.x + a0.y*gv0.y + a0.z*gv0.z + a0.w*gv0.w
                 + a1.x*gv1.x + a1.y*gv1.y + a1.z*gv1.z + a1.w*gv1.w;
        #pragma unroll
        for (int off = 16; off; off >>= 1) {
            s  += __shfl_xor_sync(0xffffffffu, s,  off);
            sq += __shfl_xor_sync(0xffffffffu, sq, off);
            sx += __shfl_xor_sync(0xffffffffu, sx, off);
        }
        const float mu   = s  * (1.f / FEAT);
        const float rstd = rsqrtf(sq * (1.f / FEAT) - mu * mu + EPS);
        const float s2   = rstd * (sx - mu * Sgv) + Sbv;   // logit

        if (s2 > m) {
            const float sc = __expf(m - s2);
            Z *= sc; Q *= sc;
            #pragma unroll
            for (int j = 0; j < 8; j++) acc[j] *= sc;
            m = s2;
        }
        const float w  = __expf(s2 - m);
        const float wr = w * rstd;
        Z += w;
        Q += wr * mu;
        acc[0] += wr * a0.x; acc[1] += wr * a0.y; acc[2] += wr * a0.z; acc[3] += wr * a0.w;
        acc[4] += wr * a1.x; acc[5] += wr * a1.y; acc[6] += wr * a1.z; acc[7] += wr * a1.w;
    }

    // ---- block combine ----
    __shared__ float sm[WARPS1], sz[WARPS1], sqq[WARPS1];
    __shared__ float sacc[FEAT];
    __shared__ float sMb, sZb, sQb;
    __shared__ int   s_old;

    for (int t = tid; t < FEAT; t += BLOCK1) sacc[t] = 0.f;
    if (lane == 0) { sm[warp] = m; sz[warp] = Z; sqq[warp] = Q; }
    __syncthreads();

    if (tid == 0) {
        float M = -CUDART_INF_F;
        #pragma unroll
        for (int w = 0; w < WARPS1; w++) M = fmaxf(M, sm[w]);
        float Zt = 0.f, Qt = 0.f;
        #pragma unroll
        for (int w = 0; w < WARPS1; w++) {
            const float sc = __expf(sm[w] - M);
            Zt += sz[w] * sc; Qt += sqq[w] * sc;
        }
        sMb = M; sZb = Zt; sQb = Qt;
    }
    __syncthreads();

    const float scb = __expf(m - sMb);
    #pragma unroll
    for (int j = 0; j < 8; j++)
        atomicAdd(&sacc[lane * 8 + j], acc[j] * scb);
    __syncthreads();

    float* pb = d_partials + blockIdx.x * 260;
    for (int t = tid; t < FEAT; t += BLOCK1) pb[t] = sacc[t];
    if (tid == 0) { pb[256] = sMb; pb[257] = sZb; pb[258] = sQb; }
    __threadfence();
    if (tid == 0) s_old = atomicAdd(&d_counter, 1);
    __syncthreads();

    // ======== merge (last-arriving block) ========
    if (s_old == GRID1 - 1) {
        __shared__ float sscale[GRID1];
        __shared__ float red[16];
        __shared__ float pooled_nf[FEAT];
        __shared__ float spool[4][ANC];
        __shared__ float pooled[ANC];
        __shared__ float sproj[8][N_ANC];
        __shared__ float na[N_ANC];
        __shared__ float sM, sZ, smu2, srstd2;

        float lm = -CUDART_INF_F;
        for (int b = tid; b < GRID1; b += BLOCK1)
            lm = fmaxf(lm, d_partials[b * 260 + 256]);
        #pragma unroll
        for (int off = 16; off; off >>= 1)
            lm = fmaxf(lm, __shfl_xor_sync(0xffffffffu, lm, off));
        if (lane == 0) red[warp] = lm;
        __syncthreads();
        if (tid == 0) {
            float M = red[0];
            #pragma unroll
            for (int w = 1; w < WARPS1; w++) M = fmaxf(M, red[w]);
            sM = M;
        }
        __syncthreads();

        float lz = 0.f, lq = 0.f;
        for (int b = tid; b < GRID1; b += BLOCK1) {
            const float sc = __expf(d_partials[b * 260 + 256] - sM);
            sscale[b] = sc;
            lz += d_partials[b * 260 + 257] * sc;
            lq += d_partials[b * 260 + 258] * sc;
        }
        #pragma unroll
        for (int off = 16; off; off >>= 1) {
            lz += __shfl_xor_sync(0xffffffffu, lz, off);
            lq += __shfl_xor_sync(0xffffffffu, lq, off);
        }
        if (lane == 0) { red[warp] = lz; sqq[warp] = lq; }
        __syncthreads();
        if (tid == 0) {
            float Zt = 0.f, Qt = 0.f;
            #pragma unroll
            for (int w = 0; w < WARPS1; w++) { Zt += red[w]; Qt += sqq[w]; }
            sZ = Zt; sQb = Qt;
        }
        __syncthreads();

        if (tid < FEAT) {
            float a = 0.f;
            #pragma unroll 8
            for (int b = 0; b < GRID1; b++)
                a += d_partials[b * 260 + tid] * sscale[b];
            pooled_nf[tid] = g_feat[tid] * (a - sQb) / sZ + b_feat[tid];
        }
        __syncthreads();

        // pooled[128] = pooled_nf @ W_send : 4 k-segments x 128 cols
        {
            const int col = tid & 127, seg = tid >> 7;
            float p = 0.f;
            #pragma unroll 8
            for (int k = seg * 64; k < seg * 64 + 64; k++)
                p += pooled_nf[k] * W_send[k * ANC + col];
            spool[seg][col] = p;
        }
        __syncthreads();
        if (tid < ANC)
            pooled[tid] = spool[0][tid] + spool[1][tid] + spool[2][tid] + spool[3][tid];
        __syncthreads();

        // proj[64] = pooled @ anchors.T : 8 c-segments x 64 rows
        {
            const int t = tid & 63, seg = tid >> 6;
            float p = 0.f;
            #pragma unroll
            for (int c = seg * 16; c < seg * 16 + 16; c++)
                p += pooled[c] * anchors[t * ANC + c];
            sproj[seg][t] = p;
        }
        __syncthreads();

        if (warp == 0) {
            float p0 = 0.f, p1 = 0.f;
            #pragma unroll
            for (int sgi = 0; sgi < 8; sgi++) { p0 += sproj[sgi][lane]; p1 += sproj[sgi][lane + 32]; }
            sproj[0][lane] = p0; sproj[0][lane + 32] = p1;
            float s = p0 + p1, sq2 = p0 * p0 + p1 * p1;
            #pragma unroll
            for (int off = 16; off; off >>= 1) {
                s   += __shfl_xor_sync(0xffffffffu, s,   off);
                sq2 += __shfl_xor_sync(0xffffffffu, sq2, off);
            }
            const float mu  = s   * (1.f / N_ANC);
            const float var = sq2 * (1.f / N_ANC) - mu * mu;
            if (lane == 0) { smu2 = mu; srstd2 = rsqrtf(var + EPS); }
        }
        __syncthreads();
        if (tid < N_ANC)
            na[tid] = (sproj[0][tid] - smu2) * srstd2 * g_anc[tid] + b_anc[tid];
        __syncthreads();

        if (tid < FEAT) {
            float r = 0.f;
            #pragma unroll 8
            for (int a2 = 0; a2 < N_ANC; a2++)
                r += na[a2] * W_recv[a2 * FEAT + tid];
            d_sr[tid] = sinf(r);
        }
        __threadfence();
        __syncthreads();
        if (tid == 0) atomicExch(&d_flag, 1);
    }

    // ======== all blocks: wait for sr, then phase 3 (reverse order) ========
    if (tid == 0) {
        while (atomicAdd(&d_flag, 0) == 0) __nanosleep(128);
    }
    __syncthreads();
    __threadfence();

    __shared__ float4 ssr[FEAT / 4];
    if (tid < FEAT / 4) ssr[tid] = ((const float4*)d_sr)[tid];
    __syncthreads();

    const long total4 = (long)N_ROWS * FEAT / 4;           // 8388608
    const long stride = (long)GRID1 * BLOCK1;              // 151552
    const float4* f4 = (const float4*)feat;
    float4* o4 = (float4*)out;
    long i = total4 - 1 - (long)(blockIdx.x * BLOCK1 + tid);
    for (; i - 3 * stride >= 0; i -= 4 * stride) {
        const long i1 = i - stride, i2 = i - 2 * stride, i3 = i - 3 * stride;
        float4 a0 = f4[i], a1 = f4[i1], a2 = f4[i2], a3 = f4[i3];
        const float4 s0 = ssr[i  & 63], s1 = ssr[i1 & 63];
        const float4 s2 = ssr[i2 & 63], s3 = ssr[i3 & 63];
        a0.x += s0.x; a0.y += s0.y; a0.z += s0.z; a0.w += s0.w;
        a1.x += s1.x; a1.y += s1.y; a1.z += s1.z; a1.w += s1.w;
        a2.x += s2.x; a2.y += s2.y; a2.z += s2.z; a2.w += s2.w;
        a3.x += s3.x; a3.y += s3.y; a3.z += s3.z; a3.w += s3.w;
        __stcs(&o4[i],  a0); __stcs(&o4[i1], a1);
        __stcs(&o4[i2], a2); __stcs(&o4[i3], a3);
    }
    for (; i >= 0; i -= stride) {
        float4 a0 = f4[i];
        const float4 s0 = ssr[i & 63];
        a0.x += s0.x; a0.y += s0.y; a0.z += s0.z; a0.w += s0.w;
        __stcs(&o4[i], a0);
    }

    // ======== self-clean for next graph replay ========
    __syncthreads();
    if (tid == 0) {
        if (atomicAdd(&d_done, 1) == GRID1 - 1) {
            d_counter = 0;
            d_flag    = 0;
            d_done    = 0;
            __threadfence();
        }
    }
}

extern "C" void kernel_launch(void* const* d_in, const int* in_sizes, int n_in,
                              void* d_out, int out_size) {
    const float* features = (const float*)d_in[0];
    const float* W_send   = (const float*)d_in[1];
    const float* a_send   = (const float*)d_in[2];
    const float* W_recv   = (const float*)d_in[3];
    // d_in[4] = a_recv (mathematically unused: second softmax is uniform)
    const float* anchors  = (const float*)d_in[5];
    const float* g_feat   = (const float*)d_in[6];
    const float* b_feat   = (const float*)d_in[7];
    const float* g_anc    = (const float*)d_in[8];
    const float* b_anc    = (const float*)d_in[9];
    float* out = (float*)d_out;

    k_main<<<GRID1, BLOCK1>>>(features, W_send, a_send, anchors,
                              g_feat, b_feat, g_anc, b_anc, W_recv, out);
}

// round 11
// speedup vs baseline: 1.1716x; 1.1716x over previous
#include <cuda_runtime.h>
#include <math_constants.h>

#define N_ROWS 131072
#define FEAT   256
#define N_ANC  64
#define ANC    128
#define EPS    1e-5f

#define GRID1  296              // 2 blocks/SM -> whole grid co-resident (spin-safe)
#define BLOCK1 512
#define WARPS1 (BLOCK1/32)
#define STEP   (GRID1*WARPS1)   // 4736 warps

// scratch (no allocs allowed)
__device__ float d_v[FEAT];                  // W_send @ a_send[128:]
__device__ float d_Sgv, d_Sbv;               // sum g*v, sum b*v
__device__ float d_partials[GRID1 * 260];    // per-block: A[256], m, Z, Q
__device__ float d_sr[FEAT];                 // sin(recv)
__device__ int   d_counter;
__device__ int   d_flag;

// ---------------- pre: ONE block.  v = W_send@a2, Sgv, Sbv, counter reset. ----------------
__global__ void k_pre(const float* __restrict__ W_send,
                      const float* __restrict__ a_send,
                      const float* __restrict__ g_feat,
                      const float* __restrict__ b_feat) {
    __shared__ float r1[8], r2[8];
    const int k = threadIdx.x;   // 256 threads
    if (k == 0) { d_counter = 0; d_flag = 0; }
    float s = 0.f;
    #pragma unroll 8
    for (int j = 0; j < ANC; j++)
        s += W_send[k * ANC + j] * a_send[ANC + j];
    d_v[k] = s;
    float p1 = g_feat[k] * s;
    float p2 = b_feat[k] * s;
    #pragma unroll
    for (int off = 16; off; off >>= 1) {
        p1 += __shfl_xor_sync(0xffffffffu, p1, off);
        p2 += __shfl_xor_sync(0xffffffffu, p2, off);
    }
    if ((k & 31) == 0) { r1[k >> 5] = p1; r2[k >> 5] = p2; }
    __syncthreads();
    if (k == 0) {
        float a = 0.f, b = 0.f;
        #pragma unroll
        for (int w = 0; w < 8; w++) { a += r1[w]; b += r2[w]; }
        d_Sgv = a; d_Sbv = b;
    }
}

// ---------------- fused main: phase1 (2-row, R5-identical hot path) + merge + phase3 ----------------
__global__ void __launch_bounds__(BLOCK1, 2)
k_main(const float* __restrict__ feat,
       const float* __restrict__ W_send,
       const float* __restrict__ anchors,
       const float* __restrict__ g_feat,
       const float* __restrict__ b_feat,
       const float* __restrict__ g_anc,
       const float* __restrict__ b_anc,
       const float* __restrict__ W_recv,
       float* __restrict__ out) {
    const int tid  = threadIdx.x;
    const int warp = tid >> 5;
    const int lane = tid & 31;
    const int gwarp = blockIdx.x * WARPS1 + warp;

    // per-lane gv constants (8 regs) — loaded from global, as in R5's 90.6us kernel
    float4 gv0, gv1;
    {
        const float4 v0 = *(const float4*)&d_v[lane * 8];
        const float4 v1 = *(const float4*)&d_v[lane * 8 + 4];
        const float4 g0 = *(const float4*)&g_feat[lane * 8];
        const float4 g1 = *(const float4*)&g_feat[lane * 8 + 4];
        gv0.x = v0.x*g0.x; gv0.y = v0.y*g0.y; gv0.z = v0.z*g0.z; gv0.w = v0.w*g0.w;
        gv1.x = v1.x*g1.x; gv1.y = v1.y*g1.y; gv1.z = v1.z*g1.z; gv1.w = v1.w*g1.w;
    }
    const float Sgv = d_Sgv, Sbv = d_Sbv;

    // ======== phase 1: 2-row pairs, interleaved reductions ========
    float m = -CUDART_INF_F, Z = 0.f, Q = 0.f;
    float acc[8];
    #pragma unroll
    for (int j = 0; j < 8; j++) acc[j] = 0.f;

    int row = gwarp;
    while (row + STEP < N_ROWS) {
        const float4* rpa = (const float4*)(feat + (size_t)row * FEAT);
        const float4* rpb = (const float4*)(feat + (size_t)(row + STEP) * FEAT);
        const float4 a0 = rpa[lane * 2], a1 = rpa[lane * 2 + 1];
        const float4 b0 = rpb[lane * 2], b1 = rpb[lane * 2 + 1];

        float sa  = a0.x + a0.y + a0.z + a0.w + a1.x + a1.y + a1.z + a1.w;
        float sqa = a0.x*a0.x + a0.y*a0.y + a0.z*a0.z + a0.w*a0.w
                  + a1.x*a1.x + a1.y*a1.y + a1.z*a1.z + a1.w*a1.w;
        float sxa = a0.x*gv0.x + a0.y*gv0.y + a0.z*gv0.z + a0.w*gv0.w
                  + a1.x*gv1.x + a1.y*gv1.y + a1.z*gv1.z + a1.w*gv1.w;
        float sb  = b0.x + b0.y + b0.z + b0.w + b1.x + b1.y + b1.z + b1.w;
        float sqb = b0.x*b0.x + b0.y*b0.y + b0.z*b0.z + b0.w*b0.w
                  + b1.x*b1.x + b1.y*b1.y + b1.z*b1.z + b1.w*b1.w;
        float sxb = b0.x*gv0.x + b0.y*gv0.y + b0.z*gv0.z + b0.w*gv0.w
                  + b1.x*gv1.x + b1.y*gv1.y + b1.z*gv1.z + b1.w*gv1.w;
        #pragma unroll
        for (int off = 16; off; off >>= 1) {   // 6 independent chains pipeline
            sa  += __shfl_xor_sync(0xffffffffu, sa,  off);
            sb  += __shfl_xor_sync(0xffffffffu, sb,  off);
            sqa += __shfl_xor_sync(0xffffffffu, sqa, off);
            sqb += __shfl_xor_sync(0xffffffffu, sqb, off);
            sxa += __shfl_xor_sync(0xffffffffu, sxa, off);
            sxb += __shfl_xor_sync(0xffffffffu, sxb, off);
        }
        const float mua   = sa  * (1.f / FEAT);
        const float mub   = sb  * (1.f / FEAT);
        const float rstda = rsqrtf(sqa * (1.f / FEAT) - mua * mua + EPS);
        const float rstdb = rsqrtf(sqb * (1.f / FEAT) - mub * mub + EPS);
        const float s2a   = rstda * (sxa - mua * Sgv) + Sbv;
        const float s2b   = rstdb * (sxb - mub * Sgv) + Sbv;

        const float mn = fmaxf(s2a, s2b);
        if (mn > m) {
            const float sc = __expf(m - mn);
            Z *= sc; Q *= sc;
            #pragma unroll
            for (int j = 0; j < 8; j++) acc[j] *= sc;
            m = mn;
        }
        const float wa = __expf(s2a - m), wb = __expf(s2b - m);
        const float wra = wa * rstda,     wrb = wb * rstdb;
        Z += wa + wb;
        Q += wra * mua + wrb * mub;
        acc[0] += wra * a0.x + wrb * b0.x;
        acc[1] += wra * a0.y + wrb * b0.y;
        acc[2] += wra * a0.z + wrb * b0.z;
        acc[3] += wra * a0.w + wrb * b0.w;
        acc[4] += wra * a1.x + wrb * b1.x;
        acc[5] += wra * a1.y + wrb * b1.y;
        acc[6] += wra * a1.z + wrb * b1.z;
        acc[7] += wra * a1.w + wrb * b1.w;

        row += 2 * STEP;
    }
    if (row < N_ROWS) {   // tail single row
        const float4* rp = (const float4*)(feat + (size_t)row * FEAT);
        const float4 a0 = rp[lane * 2], a1 = rp[lane * 2 + 1];
        float s  = a0.x + a0.y + a0.z + a0.w + a1.x + a1.y + a1.z + a1.w;
        float sq = a0.x*a0.x + a0.y*a0.y + a0.z*a0.z + a0.w*a0.w
                 + a1.x*a1.x + a1.y*a1.y + a1.z*a1.z + a1.w*a1.w;
        float sx = a0.x*gv0.x + a0.y*gv0.y + a0.z*gv0.z + a0.w*gv0.w
                 + a1.x*gv1.x + a1.y*gv1.y + a1.z*gv1.z + a1.w*gv1.w;
        #pragma unroll
        for (int off = 16; off; off >>= 1) {
            s  += __shfl_xor_sync(0xffffffffu, s,  off);
            sq += __shfl_xor_sync(0xffffffffu, sq, off);
            sx += __shfl_xor_sync(0xffffffffu, sx, off);
        }
        const float mu   = s * (1.f / FEAT);
        const float rstd = rsqrtf(sq * (1.f / FEAT) - mu * mu + EPS);
        const float s2   = rstd * (sx - mu * Sgv) + Sbv;
        if (s2 > m) {
            const float sc = __expf(m - s2);
            Z *= sc; Q *= sc;
            #pragma unroll
            for (int j = 0; j < 8; j++) acc[j] *= sc;
            m = s2;
        }
        const float w = __expf(s2 - m), wr = w * rstd;
        Z += w; Q += wr * mu;
        acc[0] += wr * a0.x; acc[1] += wr * a0.y; acc[2] += wr * a0.z; acc[3] += wr * a0.w;
        acc[4] += wr * a1.x; acc[5] += wr * a1.y; acc[6] += wr * a1.z; acc[7] += wr * a1.w;
    }

    // ---- block combine ----
    __shared__ float sm[WARPS1], sz[WARPS1], sqq[WARPS1];
    __shared__ float sacc[FEAT];
    __shared__ float sMb, sZb, sQb;
    __shared__ int   s_old;

    for (int t = tid; t < FEAT; t += BLOCK1) sacc[t] = 0.f;
    if (lane == 0) { sm[warp] = m; sz[warp] = Z; sqq[warp] = Q; }
    __syncthreads();

    if (tid == 0) {
        float M = -CUDART_INF_F;
        #pragma unroll
        for (int w = 0; w < WARPS1; w++) M = fmaxf(M, sm[w]);
        float Zt = 0.f, Qt = 0.f;
        #pragma unroll
        for (int w = 0; w < WARPS1; w++) {
            const float sc = __expf(sm[w] - M);
            Zt += sz[w] * sc; Qt += sqq[w] * sc;
        }
        sMb = M; sZb = Zt; sQb = Qt;
    }
    __syncthreads();

    const float scb = __expf(m - sMb);
    #pragma unroll
    for (int j = 0; j < 8; j++)
        atomicAdd(&sacc[lane * 8 + j], acc[j] * scb);
    __syncthreads();

    float* pb = d_partials + blockIdx.x * 260;
    for (int t = tid; t < FEAT; t += BLOCK1) pb[t] = sacc[t];
    if (tid == 0) { pb[256] = sMb; pb[257] = sZb; pb[258] = sQb; }
    __threadfence();
    if (tid == 0) s_old = atomicAdd(&d_counter, 1);
    __syncthreads();

    // ======== merge (last-arriving block) ========
    if (s_old == GRID1 - 1) {
        __shared__ float sscale[GRID1];
        __shared__ float red[16];
        __shared__ float pooled_nf[FEAT];
        __shared__ float spool[4][ANC];
        __shared__ float pooled[ANC];
        __shared__ float sproj[8][N_ANC];
        __shared__ float na[N_ANC];
        __shared__ float sM, sZ, smu2, srstd2;

        float lm = -CUDART_INF_F;
        for (int b = tid; b < GRID1; b += BLOCK1)
            lm = fmaxf(lm, d_partials[b * 260 + 256]);
        #pragma unroll
        for (int off = 16; off; off >>= 1)
            lm = fmaxf(lm, __shfl_xor_sync(0xffffffffu, lm, off));
        if (lane == 0) red[warp] = lm;
        __syncthreads();
        if (tid == 0) {
            float M = red[0];
            #pragma unroll
            for (int w = 1; w < WARPS1; w++) M = fmaxf(M, red[w]);
            sM = M;
        }
        __syncthreads();

        float lz = 0.f, lq = 0.f;
        for (int b = tid; b < GRID1; b += BLOCK1) {
            const float sc = __expf(d_partials[b * 260 + 256] - sM);
            sscale[b] = sc;
            lz += d_partials[b * 260 + 257] * sc;
            lq += d_partials[b * 260 + 258] * sc;
        }
        #pragma unroll
        for (int off = 16; off; off >>= 1) {
            lz += __shfl_xor_sync(0xffffffffu, lz, off);
            lq += __shfl_xor_sync(0xffffffffu, lq, off);
        }
        if (lane == 0) { red[warp] = lz; sqq[warp] = lq; }
        __syncthreads();
        if (tid == 0) {
            float Zt = 0.f, Qt = 0.f;
            #pragma unroll
            for (int w = 0; w < WARPS1; w++) { Zt += red[w]; Qt += sqq[w]; }
            sZ = Zt; sQb = Qt;
        }
        __syncthreads();

        if (tid < FEAT) {
            float a = 0.f;
            #pragma unroll 8
            for (int b = 0; b < GRID1; b++)
                a += d_partials[b * 260 + tid] * sscale[b];
            pooled_nf[tid] = g_feat[tid] * (a - sQb) / sZ + b_feat[tid];
        }
        __syncthreads();

        // pooled[128] = pooled_nf @ W_send : 4 k-segments x 128 cols
        {
            const int col = tid & 127, seg = tid >> 7;
            float p = 0.f;
            #pragma unroll 8
            for (int k = seg * 64; k < seg * 64 + 64; k++)
                p += pooled_nf[k] * W_send[k * ANC + col];
            spool[seg][col] = p;
        }
        __syncthreads();
        if (tid < ANC)
            pooled[tid] = spool[0][tid] + spool[1][tid] + spool[2][tid] + spool[3][tid];
        __syncthreads();

        // proj[64] = pooled @ anchors.T : 8 c-segments x 64 rows
        {
            const int t = tid & 63, seg = tid >> 6;
            float p = 0.f;
            #pragma unroll
            for (int c = seg * 16; c < seg * 16 + 16; c++)
                p += pooled[c] * anchors[t * ANC + c];
            sproj[seg][t] = p;
        }
        __syncthreads();

        if (warp == 0) {
            float p0 = 0.f, p1 = 0.f;
            #pragma unroll
            for (int sgi = 0; sgi < 8; sgi++) { p0 += sproj[sgi][lane]; p1 += sproj[sgi][lane + 32]; }
            sproj[0][lane] = p0; sproj[0][lane + 32] = p1;
            float s = p0 + p1, sq2 = p0 * p0 + p1 * p1;
            #pragma unroll
            for (int off = 16; off; off >>= 1) {
                s   += __shfl_xor_sync(0xffffffffu, s,   off);
                sq2 += __shfl_xor_sync(0xffffffffu, sq2, off);
            }
            const float mu  = s   * (1.f / N_ANC);
            const float var = sq2 * (1.f / N_ANC) - mu * mu;
            if (lane == 0) { smu2 = mu; srstd2 = rsqrtf(var + EPS); }
        }
        __syncthreads();
        if (tid < N_ANC)
            na[tid] = (sproj[0][tid] - smu2) * srstd2 * g_anc[tid] + b_anc[tid];
        __syncthreads();

        if (tid < FEAT) {
            float r = 0.f;
            #pragma unroll 8
            for (int a2 = 0; a2 < N_ANC; a2++)
                r += na[a2] * W_recv[a2 * FEAT + tid];
            d_sr[tid] = sinf(r);
        }
        __threadfence();
        __syncthreads();
        if (tid == 0) atomicExch(&d_flag, 1);
    }

    // ======== all blocks: wait for sr, then phase 3 (reverse order) ========
    if (tid == 0) {
        while (atomicAdd(&d_flag, 0) == 0) __nanosleep(128);
    }
    __syncthreads();
    __threadfence();

    __shared__ float4 ssr[FEAT / 4];
    if (tid < FEAT / 4) ssr[tid] = ((const float4*)d_sr)[tid];
    __syncthreads();

    const long total4 = (long)N_ROWS * FEAT / 4;           // 8388608
    const long stride = (long)GRID1 * BLOCK1;              // 151552
    const float4* f4 = (const float4*)feat;
    float4* o4 = (float4*)out;
    long i = total4 - 1 - (long)(blockIdx.x * BLOCK1 + tid);
    for (; i - 3 * stride >= 0; i -= 4 * stride) {
        const long i1 = i - stride, i2 = i - 2 * stride, i3 = i - 3 * stride;
        float4 a0 = f4[i], a1 = f4[i1], a2 = f4[i2], a3 = f4[i3];
        const float4 s0 = ssr[i  & 63], s1 = ssr[i1 & 63];
        const float4 s2 = ssr[i2 & 63], s3 = ssr[i3 & 63];
        a0.x += s0.x; a0.y += s0.y; a0.z += s0.z; a0.w += s0.w;
        a1.x += s1.x; a1.y += s1.y; a1.z += s1.z; a1.w += s1.w;
        a2.x += s2.x; a2.y += s2.y; a2.z += s2.z; a2.w += s2.w;
        a3.x += s3.x; a3.y += s3.y; a3.z += s3.z; a3.w += s3.w;
        __stcs(&o4[i],  a0); __stcs(&o4[i1], a1);
        __stcs(&o4[i2], a2); __stcs(&o4[i3], a3);
    }
    for (; i >= 0; i -= stride) {
        float4 a0 = f4[i];
        const float4 s0 = ssr[i & 63];
        a0.x += s0.x; a0.y += s0.y; a0.z += s0.z; a0.w += s0.w;
        __stcs(&o4[i], a0);
    }
}

extern "C" void kernel_launch(void* const* d_in, const int* in_sizes, int n_in,
                              void* d_out, int out_size) {
    const float* features = (const float*)d_in[0];
    const float* W_send   = (const float*)d_in[1];
    const float* a_send   = (const float*)d_in[2];
    const float* W_recv   = (const float*)d_in[3];
    // d_in[4] = a_recv (mathematically unused: second softmax is uniform)
    const float* anchors  = (const float*)d_in[5];
    const float* g_feat   = (const float*)d_in[6];
    const float* b_feat   = (const float*)d_in[7];
    const float* g_anc    = (const float*)d_in[8];
    const float* b_anc    = (const float*)d_in[9];
    float* out = (float*)d_out;

    k_pre<<<1, 256>>>(W_send, a_send, g_feat, b_feat);
    k_main<<<GRID1, BLOCK1>>>(features, W_send, anchors,
                              g_feat, b_feat, g_anc, b_anc, W_recv, out);
}

// round 13
// speedup vs baseline: 1.2924x; 1.1031x over previous
#include <cuda_runtime.h>
#include <math_constants.h>

#define N_ROWS 131072
#define FEAT   256
#define N_ANC  64
#define ANC    128
#define EPS    1e-5f

#define GRID1  296              // 2 blocks/SM -> whole grid co-resident (spin-safe)
#define BLOCK1 512
#define WARPS1 (BLOCK1/32)
#define STEP   (GRID1*WARPS1)   // 4736 warps

// scratch (no allocs allowed)
__device__ float d_v[FEAT];                  // W_send @ a_send[128:]
__device__ float d_Sgv, d_Sbv;               // sum g*v, sum b*v
__device__ float d_partials[GRID1 * 260];    // per-block: A[256], m, Z, Q
__device__ float d_sr[FEAT];                 // sin(recv)
__device__ int   d_counter;
__device__ int   d_flag;

// ---------------- pre: ONE block, vectorized.  v = W_send@a2, Sgv, Sbv, resets. ----------------
__global__ void k_pre(const float* __restrict__ W_send,
                      const float* __restrict__ a_send,
                      const float* __restrict__ g_feat,
                      const float* __restrict__ b_feat) {
    __shared__ float sa2[ANC];
    __shared__ float r1[8], r2[8];
    const int k = threadIdx.x;   // 256 threads
    if (k == 0) { d_counter = 0; d_flag = 0; }
    if (k < ANC) sa2[k] = a_send[ANC + k];
    __syncthreads();

    // row k of W_send: 32 float4 loads, fully unrolled -> high MLP
    const float4* wr = (const float4*)(W_send + (size_t)k * ANC);
    float s = 0.f;
    #pragma unroll
    for (int j = 0; j < ANC / 4; j++) {
        const float4 w = wr[j];
        s += w.x * sa2[4*j]   + w.y * sa2[4*j+1]
           + w.z * sa2[4*j+2] + w.w * sa2[4*j+3];
    }
    d_v[k] = s;

    float p1 = g_feat[k] * s;
    float p2 = b_feat[k] * s;
    #pragma unroll
    for (int off = 16; off; off >>= 1) {
        p1 += __shfl_xor_sync(0xffffffffu, p1, off);
        p2 += __shfl_xor_sync(0xffffffffu, p2, off);
    }
    if ((k & 31) == 0) { r1[k >> 5] = p1; r2[k >> 5] = p2; }
    __syncthreads();
    if (k == 0) {
        float a = 0.f, b = 0.f;
        #pragma unroll
        for (int w = 0; w < 8; w++) { a += r1[w]; b += r2[w]; }
        d_Sgv = a; d_Sbv = b;
    }
}

// ---------------- fused main: phase1 (2-row) + merge + phase3  (UNCHANGED measured-best) ----------------
__global__ void __launch_bounds__(BLOCK1, 2)
k_main(const float* __restrict__ feat,
       const float* __restrict__ W_send,
       const float* __restrict__ anchors,
       const float* __restrict__ g_feat,
       const float* __restrict__ b_feat,
       const float* __restrict__ g_anc,
       const float* __restrict__ b_anc,
       const float* __restrict__ W_recv,
       float* __restrict__ out) {
    const int tid  = threadIdx.x;
    const int warp = tid >> 5;
    const int lane = tid & 31;
    const int gwarp = blockIdx.x * WARPS1 + warp;

    // per-lane gv constants (8 regs)
    float4 gv0, gv1;
    {
        const float4 v0 = *(const float4*)&d_v[lane * 8];
        const float4 v1 = *(const float4*)&d_v[lane * 8 + 4];
        const float4 g0 = *(const float4*)&g_feat[lane * 8];
        const float4 g1 = *(const float4*)&g_feat[lane * 8 + 4];
        gv0.x = v0.x*g0.x; gv0.y = v0.y*g0.y; gv0.z = v0.z*g0.z; gv0.w = v0.w*g0.w;
        gv1.x = v1.x*g1.x; gv1.y = v1.y*g1.y; gv1.z = v1.z*g1.z; gv1.w = v1.w*g1.w;
    }
    const float Sgv = d_Sgv, Sbv = d_Sbv;

    // ======== phase 1: 2-row pairs, interleaved reductions ========
    float m = -CUDART_INF_F, Z = 0.f, Q = 0.f;
    float acc[8];
    #pragma unroll
    for (int j = 0; j < 8; j++) acc[j] = 0.f;

    int row = gwarp;
    while (row + STEP < N_ROWS) {
        const float4* rpa = (const float4*)(feat + (size_t)row * FEAT);
        const float4* rpb = (const float4*)(feat + (size_t)(row + STEP) * FEAT);
        const float4 a0 = rpa[lane * 2], a1 = rpa[lane * 2 + 1];
        const float4 b0 = rpb[lane * 2], b1 = rpb[lane * 2 + 1];

        float sa  = a0.x + a0.y + a0.z + a0.w + a1.x + a1.y + a1.z + a1.w;
        float sqa = a0.x*a0.x + a0.y*a0.y + a0.z*a0.z + a0.w*a0.w
                  + a1.x*a1.x + a1.y*a1.y + a1.z*a1.z + a1.w*a1.w;
        float sxa = a0.x*gv0.x + a0.y*gv0.y + a0.z*gv0.z + a0.w*gv0.w
                  + a1.x*gv1.x + a1.y*gv1.y + a1.z*gv1.z + a1.w*gv1.w;
        float sb  = b0.x + b0.y + b0.z + b0.w + b1.x + b1.y + b1.z + b1.w;
        float sqb = b0.x*b0.x + b0.y*b0.y + b0.z*b0.z + b0.w*b0.w
                  + b1.x*b1.x + b1.y*b1.y + b1.z*b1.z + b1.w*b1.w;
        float sxb = b0.x*gv0.x + b0.y*gv0.y + b0.z*gv0.z + b0.w*gv0.w
                  + b1.x*gv1.x + b1.y*gv1.y + b1.z*gv1.z + b1.w*gv1.w;
        #pragma unroll
        for (int off = 16; off; off >>= 1) {   // 6 independent chains pipeline
            sa  += __shfl_xor_sync(0xffffffffu, sa,  off);
            sb  += __shfl_xor_sync(0xffffffffu, sb,  off);
            sqa += __shfl_xor_sync(0xffffffffu, sqa, off);
            sqb += __shfl_xor_sync(0xffffffffu, sqb, off);
            sxa += __shfl_xor_sync(0xffffffffu, sxa, off);
            sxb += __shfl_xor_sync(0xffffffffu, sxb, off);
        }
        const float mua   = sa  * (1.f / FEAT);
        const float mub   = sb  * (1.f / FEAT);
        const float rstda = rsqrtf(sqa * (1.f / FEAT) - mua * mua + EPS);
        const float rstdb = rsqrtf(sqb * (1.f / FEAT) - mub * mub + EPS);
        const float s2a   = rstda * (sxa - mua * Sgv) + Sbv;
        const float s2b   = rstdb * (sxb - mub * Sgv) + Sbv;

        const float mn = fmaxf(s2a, s2b);
        if (mn > m) {
            const float sc = __expf(m - mn);
            Z *= sc; Q *= sc;
            #pragma unroll
            for (int j = 0; j < 8; j++) acc[j] *= sc;
            m = mn;
        }
        const float wa = __expf(s2a - m), wb = __expf(s2b - m);
        const float wra = wa * rstda,     wrb = wb * rstdb;
        Z += wa + wb;
        Q += wra * mua + wrb * mub;
        acc[0] += wra * a0.x + wrb * b0.x;
        acc[1] += wra * a0.y + wrb * b0.y;
        acc[2] += wra * a0.z + wrb * b0.z;
        acc[3] += wra * a0.w + wrb * b0.w;
        acc[4] += wra * a1.x + wrb * b1.x;
        acc[5] += wra * a1.y + wrb * b1.y;
        acc[6] += wra * a1.z + wrb * b1.z;
        acc[7] += wra * a1.w + wrb * b1.w;

        row += 2 * STEP;
    }
    if (row < N_ROWS) {   // tail single row
        const float4* rp = (const float4*)(feat + (size_t)row * FEAT);
        const float4 a0 = rp[lane * 2], a1 = rp[lane * 2 + 1];
        float s  = a0.x + a0.y + a0.z + a0.w + a1.x + a1.y + a1.z + a1.w;
        float sq = a0.x*a0.x + a0.y*a0.y + a0.z*a0.z + a0.w*a0.w
                 + a1.x*a1.x + a1.y*a1.y + a1.z*a1.z + a1.w*a1.w;
        float sx = a0.x*gv0.x + a0.y*gv0.y + a0.z*gv0.z + a0.w*gv0.w
                 + a1.x*gv1.x + a1.y*gv1.y + a1.z*gv1.z + a1.w*gv1.w;
        #pragma unroll
        for (int off = 16; off; off >>= 1) {
            s  += __shfl_xor_sync(0xffffffffu, s,  off);
            sq += __shfl_xor_sync(0xffffffffu, sq, off);
            sx += __shfl_xor_sync(0xffffffffu, sx, off);
        }
        const float mu   = s * (1.f / FEAT);
        const float rstd = rsqrtf(sq * (1.f / FEAT) - mu * mu + EPS);
        const float s2   = rstd * (sx - mu * Sgv) + Sbv;
        if (s2 > m) {
            const float sc = __expf(m - s2);
            Z *= sc; Q *= sc;
            #pragma unroll
            for (int j = 0; j < 8; j++) acc[j] *= sc;
            m = s2;
        }
        const float w = __expf(s2 - m), wr = w * rstd;
        Z += w; Q += wr * mu;
        acc[0] += wr * a0.x; acc[1] += wr * a0.y; acc[2] += wr * a0.z; acc[3] += wr * a0.w;
        acc[4] += wr * a1.x; acc[5] += wr * a1.y; acc[6] += wr * a1.z; acc[7] += wr * a1.w;
    }

    // ---- block combine ----
    __shared__ float sm[WARPS1], sz[WARPS1], sqq[WARPS1];
    __shared__ float sacc[FEAT];
    __shared__ float sMb, sZb, sQb;
    __shared__ int   s_old;

    for (int t = tid; t < FEAT; t += BLOCK1) sacc[t] = 0.f;
    if (lane == 0) { sm[warp] = m; sz[warp] = Z; sqq[warp] = Q; }
    __syncthreads();

    if (tid == 0) {
        float M = -CUDART_INF_F;
        #pragma unroll
        for (int w = 0; w < WARPS1; w++) M = fmaxf(M, sm[w]);
        float Zt = 0.f, Qt = 0.f;
        #pragma unroll
        for (int w = 0; w < WARPS1; w++) {
            const float sc = __expf(sm[w] - M);
            Zt += sz[w] * sc; Qt += sqq[w] * sc;
        }
        sMb = M; sZb = Zt; sQb = Qt;
    }
    __syncthreads();

    const float scb = __expf(m - sMb);
    #pragma unroll
    for (int j = 0; j < 8; j++)
        atomicAdd(&sacc[lane * 8 + j], acc[j] * scb);
    __syncthreads();

    float* pb = d_partials + blockIdx.x * 260;
    for (int t = tid; t < FEAT; t += BLOCK1) pb[t] = sacc[t];
    if (tid == 0) { pb[256] = sMb; pb[257] = sZb; pb[258] = sQb; }
    __threadfence();
    if (tid == 0) s_old = atomicAdd(&d_counter, 1);
    __syncthreads();

    // ======== merge (last-arriving block) ========
    if (s_old == GRID1 - 1) {
        __shared__ float sscale[GRID1];
        __shared__ float red[16];
        __shared__ float pooled_nf[FEAT];
        __shared__ float spool[4][ANC];
        __shared__ float pooled[ANC];
        __shared__ float sproj[8][N_ANC];
        __shared__ float na[N_ANC];
        __shared__ float sM, sZ, smu2, srstd2;

        float lm = -CUDART_INF_F;
        for (int b = tid; b < GRID1; b += BLOCK1)
            lm = fmaxf(lm, d_partials[b * 260 + 256]);
        #pragma unroll
        for (int off = 16; off; off >>= 1)
            lm = fmaxf(lm, __shfl_xor_sync(0xffffffffu, lm, off));
        if (lane == 0) red[warp] = lm;
        __syncthreads();
        if (tid == 0) {
            float M = red[0];
            #pragma unroll
            for (int w = 1; w < WARPS1; w++) M = fmaxf(M, red[w]);
            sM = M;
        }
        __syncthreads();

        float lz = 0.f, lq = 0.f;
        for (int b = tid; b < GRID1; b += BLOCK1) {
            const float sc = __expf(d_partials[b * 260 + 256] - sM);
            sscale[b] = sc;
            lz += d_partials[b * 260 + 257] * sc;
            lq += d_partials[b * 260 + 258] * sc;
        }
        #pragma unroll
        for (int off = 16; off; off >>= 1) {
            lz += __shfl_xor_sync(0xffffffffu, lz, off);
            lq += __shfl_xor_sync(0xffffffffu, lq, off);
        }
        if (lane == 0) { red[warp] = lz; sqq[warp] = lq; }
        __syncthreads();
        if (tid == 0) {
            float Zt = 0.f, Qt = 0.f;
            #pragma unroll
            for (int w = 0; w < WARPS1; w++) { Zt += red[w]; Qt += sqq[w]; }
            sZ = Zt; sQb = Qt;
        }
        __syncthreads();

        if (tid < FEAT) {
            float a = 0.f;
            #pragma unroll 8
            for (int b = 0; b < GRID1; b++)
                a += d_partials[b * 260 + tid] * sscale[b];
            pooled_nf[tid] = g_feat[tid] * (a - sQb) / sZ + b_feat[tid];
        }
        __syncthreads();

        // pooled[128] = pooled_nf @ W_send : 4 k-segments x 128 cols
        {
            const int col = tid & 127, seg = tid >> 7;
            float p = 0.f;
            #pragma unroll 8
            for (int k = seg * 64; k < seg * 64 + 64; k++)
                p += pooled_nf[k] * W_send[k * ANC + col];
            spool[seg][col] = p;
        }
        __syncthreads();
        if (tid < ANC)
            pooled[tid] = spool[0][tid] + spool[1][tid] + spool[2][tid] + spool[3][tid];
        __syncthreads();

        // proj[64] = pooled @ anchors.T : 8 c-segments x 64 rows
        {
            const int t = tid & 63, seg = tid >> 6;
            float p = 0.f;
            #pragma unroll
            for (int c = seg * 16; c < seg * 16 + 16; c++)
                p += pooled[c] * anchors[t * ANC + c];
            sproj[seg][t] = p;
        }
        __syncthreads();

        if (warp == 0) {
            float p0 = 0.f, p1 = 0.f;
            #pragma unroll
            for (int sgi = 0; sgi < 8; sgi++) { p0 += sproj[sgi][lane]; p1 += sproj[sgi][lane + 32]; }
            sproj[0][lane] = p0; sproj[0][lane + 32] = p1;
            float s = p0 + p1, sq2 = p0 * p0 + p1 * p1;
            #pragma unroll
            for (int off = 16; off; off >>= 1) {
                s   += __shfl_xor_sync(0xffffffffu, s,   off);
                sq2 += __shfl_xor_sync(0xffffffffu, sq2, off);
            }
            const float mu  = s   * (1.f / N_ANC);
            const float var = sq2 * (1.f / N_ANC) - mu * mu;
            if (lane == 0) { smu2 = mu; srstd2 = rsqrtf(var + EPS); }
        }
        __syncthreads();
        if (tid < N_ANC)
            na[tid] = (sproj[0][tid] - smu2) * srstd2 * g_anc[tid] + b_anc[tid];
        __syncthreads();

        if (tid < FEAT) {
            float r = 0.f;
            #pragma unroll 8
            for (int a2 = 0; a2 < N_ANC; a2++)
                r += na[a2] * W_recv[a2 * FEAT + tid];
            d_sr[tid] = sinf(r);
        }
        __threadfence();
        __syncthreads();
        if (tid == 0) atomicExch(&d_flag, 1);
    }

    // ======== all blocks: wait for sr, then phase 3 (reverse order) ========
    if (tid == 0) {
        while (atomicAdd(&d_flag, 0) == 0) __nanosleep(128);
    }
    __syncthreads();
    __threadfence();

    __shared__ float4 ssr[FEAT / 4];
    if (tid < FEAT / 4) ssr[tid] = ((const float4*)d_sr)[tid];
    __syncthreads();

    const long total4 = (long)N_ROWS * FEAT / 4;           // 8388608
    const long stride = (long)GRID1 * BLOCK1;              // 151552
    const float4* f4 = (const float4*)feat;
    float4* o4 = (float4*)out;
    long i = total4 - 1 - (long)(blockIdx.x * BLOCK1 + tid);
    for (; i - 3 * stride >= 0; i -= 4 * stride) {
        const long i1 = i - stride, i2 = i - 2 * stride, i3 = i - 3 * stride;
        float4 a0 = f4[i], a1 = f4[i1], a2 = f4[i2], a3 = f4[i3];
        const float4 s0 = ssr[i  & 63], s1 = ssr[i1 & 63];
        const float4 s2 = ssr[i2 & 63], s3 = ssr[i3 & 63];
        a0.x += s0.x; a0.y += s0.y; a0.z += s0.z; a0.w += s0.w;
        a1.x += s1.x; a1.y += s1.y; a1.z += s1.z; a1.w += s1.w;
        a2.x += s2.x; a2.y += s2.y; a2.z += s2.z; a2.w += s2.w;
        a3.x += s3.x; a3.y += s3.y; a3.z += s3.z; a3.w += s3.w;
        __stcs(&o4[i],  a0); __stcs(&o4[i1], a1);
        __stcs(&o4[i2], a2); __stcs(&o4[i3], a3);
    }
    for (; i >= 0; i -= stride) {
        float4 a0 = f4[i];
        const float4 s0 = ssr[i & 63];
        a0.x += s0.x; a0.y += s0.y; a0.z += s0.z; a0.w += s0.w;
        __stcs(&o4[i], a0);
    }
}

extern "C" void kernel_launch(void* const* d_in, const int* in_sizes, int n_in,
                              void* d_out, int out_size) {
    const float* features = (const float*)d_in[0];
    const float* W_send   = (const float*)d_in[1];
    const float* a_send   = (const float*)d_in[2];
    const float* W_recv   = (const float*)d_in[3];
    // d_in[4] = a_recv (mathematically unused: second softmax is uniform)
    const float* anchors  = (const float*)d_in[5];
    const float* g_feat   = (const float*)d_in[6];
    const float* b_feat   = (const float*)d_in[7];
    const float* g_anc    = (const float*)d_in[8];
    const float* b_anc    = (const float*)d_in[9];
    float* out = (float*)d_out;

    k_pre<<<1, 256>>>(W_send, a_send, g_feat, b_feat);
    k_main<<<GRID1, BLOCK1>>>(features, W_send, anchors,
                              g_feat, b_feat, g_anc, b_anc, W_recv, out);
}